// round 1
// baseline (speedup 1.0000x reference)
#include <cuda_runtime.h>
#include <cuda_bf16.h>

// ---------------- problem constants ----------------
#define BATCH 2
#define CCH   256          // channels C
#define NSP   32768        // N = D*H*W = 32^3
#define NHEAD 8
#define HD    32           // head dim
#define GRP   32           // groupnorm groups
#define CPG   8            // channels per group
#define MQKV  768          // 3*C
#define EPS   1e-5f
#define KVSPLIT 64

// ---------------- static scratch (no cudaMalloc allowed) ----------------
__device__ float g_qkv[(size_t)BATCH * MQKV * NSP];   // 192 MB: q|k|v, q overwritten by attn-out
__device__ float g_proj[(size_t)BATCH * CCH * NSP];   // 64 MB
__device__ float g_mu1[BATCH * GRP];
__device__ float g_rstd1[BATCH * GRP];
__device__ float g_mu2[BATCH * GRP];
__device__ float g_rstd2[BATCH * GRP];
__device__ float g_scale1[BATCH * CCH];
__device__ float g_shift1[BATCH * CCH];
__device__ float g_invs[BATCH * CCH];    // 1 / clip(rowsum(k), 1e-6)   per (b, h*32+d)
__device__ float g_ksumA[BATCH * CCH];   // rowsum / clip(rowsum)  (== k.sum after norm)
__device__ float g_kvpart[(size_t)KVSPLIT * 16 * 1024]; // split-K partials (deterministic)
__device__ float g_kv[BATCH * NHEAD * HD * HD];

// ---------------- helpers ----------------
__device__ __forceinline__ float warp_sum(float v) {
    #pragma unroll
    for (int o = 16; o; o >>= 1) v += __shfl_xor_sync(0xffffffffu, v, o);
    return v;
}

// ---------------- group-norm stats (stage 0: over x, stage 1: over g_proj) ----------------
template<int STAGE>
__global__ void gn_stats_kernel(const float* __restrict__ xsrc) {
    const float* src = (STAGE == 0) ? xsrc : g_proj;
    int grp = blockIdx.x;  // b*GRP + g ; group channels are contiguous rows
    const float4* base = (const float4*)(src + (size_t)grp * CPG * NSP);
    const int M4 = CPG * NSP / 4;
    float s = 0.f, s2 = 0.f;
    for (int i = threadIdx.x; i < M4; i += 256) {
        float4 v = base[i];
        s  += (v.x + v.y) + (v.z + v.w);
        s2 += v.x * v.x + v.y * v.y + v.z * v.z + v.w * v.w;
    }
    __shared__ float sh[8], sh2[8];
    s = warp_sum(s); s2 = warp_sum(s2);
    int w = threadIdx.x >> 5, l = threadIdx.x & 31;
    if (l == 0) { sh[w] = s; sh2[w] = s2; }
    __syncthreads();
    if (w == 0) {
        s  = (l < 8) ? sh[l]  : 0.f;
        s2 = (l < 8) ? sh2[l] : 0.f;
        s = warp_sum(s); s2 = warp_sum(s2);
        if (l == 0) {
            const float inv = 1.0f / (float)(CPG * NSP);
            float mu  = s * inv;
            float var = s2 * inv - mu * mu;
            float rs  = rsqrtf(var + EPS);
            if (STAGE == 0) { g_mu1[grp] = mu; g_rstd1[grp] = rs; }
            else            { g_mu2[grp] = mu; g_rstd2[grp] = rs; }
        }
    }
}

// ---------------- per-channel affine for GN1 (folded into qkv GEMM B-load) ----------------
__global__ void prep_kernel(const float* __restrict__ nw, const float* __restrict__ nb) {
    int i = blockIdx.x * 256 + threadIdx.x;
    if (i < BATCH * CCH) {
        int b = i / CCH, c = i % CCH;
        float mu = g_mu1[b * GRP + c / CPG];
        float r  = g_rstd1[b * GRP + c / CPG];
        float sc = r * nw[c];
        g_scale1[i] = sc;
        g_shift1[i] = nb[c] - mu * sc;
    }
}

// ---------------- tiled SGEMM: C[M,NSP] = A[M,256] @ B[256,NSP] + bias ----------------
// MODE 0: B = groupnorm(x) on the fly, C = g_qkv, elu+1 applied to rows < 512 (q,k)
// MODE 1: B = g_qkv q-region (attn result), C = g_proj
template<int MODE>
__global__ void __launch_bounds__(256) gemm_kernel(
    const float* __restrict__ A, const float* __restrict__ Bsrc,
    const float* __restrict__ bias)
{
    __shared__ float As[16][128];
    __shared__ float Bs[16][128];

    const int bz = blockIdx.z;
    const int mt = blockIdx.y;
    const int nt = blockIdx.x;
    const int t  = threadIdx.x;
    const int tx = t & 15, ty = t >> 4;

    const float* Ab;
    const float* Bb;
    float* Cd;
    Ab = A + (size_t)mt * 128 * CCH;
    if (MODE == 0) {
        Bb = Bsrc + (size_t)bz * CCH * NSP + (size_t)nt * 128;
        Cd = g_qkv + ((size_t)bz * MQKV + (size_t)mt * 128) * NSP + (size_t)nt * 128;
    } else {
        Bb = g_qkv + (size_t)bz * MQKV * NSP + (size_t)nt * 128;   // q region rows [0,256)
        Cd = g_proj + ((size_t)bz * CCH + (size_t)mt * 128) * NSP + (size_t)nt * 128;
    }

    float acc[8][8];
    #pragma unroll
    for (int i = 0; i < 8; i++)
        #pragma unroll
        for (int j = 0; j < 8; j++) acc[i][j] = 0.f;

    for (int k0 = 0; k0 < CCH; k0 += 16) {
        // load A tile 128x16 (transpose into As[k][m])
        #pragma unroll
        for (int it = 0; it < 2; it++) {
            int f = t + it * 256;
            int r = f >> 2, c4 = (f & 3) << 2;
            float4 a4 = *(const float4*)(Ab + (size_t)r * CCH + k0 + c4);
            As[c4 + 0][r] = a4.x; As[c4 + 1][r] = a4.y;
            As[c4 + 2][r] = a4.z; As[c4 + 3][r] = a4.w;
        }
        // load B tile 16x128
        #pragma unroll
        for (int it = 0; it < 2; it++) {
            int f = t + it * 256;
            int r = f >> 5, c4 = (f & 31) << 2;
            float4 b4 = *(const float4*)(Bb + (size_t)(k0 + r) * NSP + c4);
            if (MODE == 0) {
                int c = k0 + r;
                float sc = g_scale1[bz * CCH + c];
                float sh = g_shift1[bz * CCH + c];
                b4.x = fmaf(b4.x, sc, sh);
                b4.y = fmaf(b4.y, sc, sh);
                b4.z = fmaf(b4.z, sc, sh);
                b4.w = fmaf(b4.w, sc, sh);
            }
            *(float4*)&Bs[r][c4] = b4;
        }
        __syncthreads();

        #pragma unroll
        for (int k = 0; k < 16; k++) {
            float ra[8], rb[8];
            *(float4*)&ra[0] = *(const float4*)&As[k][ty * 8];
            *(float4*)&ra[4] = *(const float4*)&As[k][ty * 8 + 4];
            *(float4*)&rb[0] = *(const float4*)&Bs[k][tx * 8];
            *(float4*)&rb[4] = *(const float4*)&Bs[k][tx * 8 + 4];
            #pragma unroll
            for (int i = 0; i < 8; i++)
                #pragma unroll
                for (int j = 0; j < 8; j++)
                    acc[i][j] = fmaf(ra[i], rb[j], acc[i][j]);
        }
        __syncthreads();
    }

    // epilogue
    #pragma unroll
    for (int i = 0; i < 8; i++) {
        int o = mt * 128 + ty * 8 + i;
        float bi = bias[o];
        float v[8];
        #pragma unroll
        for (int j = 0; j < 8; j++) v[j] = acc[i][j] + bi;
        if (MODE == 0 && o < 512) {  // q and k rows: elu(x)+1
            #pragma unroll
            for (int j = 0; j < 8; j++) v[j] = (v[j] > 0.f) ? (v[j] + 1.f) : __expf(v[j]);
        }
        float* crow = Cd + (size_t)(ty * 8 + i) * NSP + tx * 8;
        *(float4*)crow       = make_float4(v[0], v[1], v[2], v[3]);
        *(float4*)(crow + 4) = make_float4(v[4], v[5], v[6], v[7]);
    }
}

// ---------------- k row-sums -> 1/clip(s), s/clip(s) ----------------
__global__ void krowsum_kernel() {
    int row = blockIdx.x;               // 0..511
    int b = row >> 8, r = row & 255;
    const float4* base = (const float4*)(g_qkv + ((size_t)b * MQKV + 256 + r) * NSP);
    float s = 0.f;
    for (int i = threadIdx.x; i < NSP / 4; i += 256) {
        float4 v = base[i];
        s += (v.x + v.y) + (v.z + v.w);
    }
    __shared__ float sh[8];
    s = warp_sum(s);
    int w = threadIdx.x >> 5, l = threadIdx.x & 31;
    if (l == 0) sh[w] = s;
    __syncthreads();
    if (w == 0) {
        s = (l < 8) ? sh[l] : 0.f;
        s = warp_sum(s);
        if (l == 0) {
            float cs = fmaxf(s, 1e-6f);
            g_invs[row]  = 1.0f / cs;
            g_ksumA[row] = s / cs;
        }
    }
}

// ---------------- kv = (k/clip)·v^T, split-K partials (deterministic) ----------------
__global__ void __launch_bounds__(256) kv_kernel() {
    int bh = blockIdx.x;                // 0..15
    int split = blockIdx.y;             // 0..63, each covers 512 columns
    int b = bh >> 3, h = bh & 7;

    __shared__ float ks[32][129];
    __shared__ float vs[32][129];

    const float* kbase = g_qkv + ((size_t)b * MQKV + 256 + h * HD) * NSP + (size_t)split * 512;
    const float* vbase = g_qkv + ((size_t)b * MQKV + 512 + h * HD) * NSP + (size_t)split * 512;

    int t = threadIdx.x;
    int d0 = (t >> 4) << 1;             // 0,2,..30
    int e0 = (t & 15) << 1;

    float a00 = 0.f, a01 = 0.f, a10 = 0.f, a11 = 0.f;

    for (int ch = 0; ch < 4; ch++) {
        __syncthreads();
        #pragma unroll
        for (int it = 0; it < 4; it++) {
            int f = t + it * 256;
            int dr = f >> 5, dc = (f & 31) << 2;
            float4 kk = *(const float4*)(kbase + (size_t)dr * NSP + ch * 128 + dc);
            ks[dr][dc + 0] = kk.x; ks[dr][dc + 1] = kk.y;
            ks[dr][dc + 2] = kk.z; ks[dr][dc + 3] = kk.w;
            float4 vv = *(const float4*)(vbase + (size_t)dr * NSP + ch * 128 + dc);
            vs[dr][dc + 0] = vv.x; vs[dr][dc + 1] = vv.y;
            vs[dr][dc + 2] = vv.z; vs[dr][dc + 3] = vv.w;
        }
        __syncthreads();
        #pragma unroll 4
        for (int n = 0; n < 128; n++) {
            float k0v = ks[d0][n],     k1v = ks[d0 + 1][n];
            float v0v = vs[e0][n],     v1v = vs[e0 + 1][n];
            a00 = fmaf(k0v, v0v, a00); a01 = fmaf(k0v, v1v, a01);
            a10 = fmaf(k1v, v0v, a10); a11 = fmaf(k1v, v1v, a11);
        }
    }

    float i0 = g_invs[b * CCH + h * HD + d0];
    float i1 = g_invs[b * CCH + h * HD + d0 + 1];
    float* dst = g_kvpart + ((size_t)split * 16 + bh) * 1024;
    dst[(d0    ) * 32 + e0    ] = a00 * i0;
    dst[(d0    ) * 32 + e0 + 1] = a01 * i0;
    dst[(d0 + 1) * 32 + e0    ] = a10 * i1;
    dst[(d0 + 1) * 32 + e0 + 1] = a11 * i1;
}

__global__ void kvreduce_kernel() {
    int i = blockIdx.x * 256 + threadIdx.x;   // 0..16383 : bh*1024 + de
    if (i >= 16 * 1024) return;
    int bh = i >> 10, de = i & 1023;
    float s = 0.f;
    #pragma unroll 8
    for (int sp = 0; sp < KVSPLIT; sp++)
        s += g_kvpart[((size_t)sp * 16 + bh) * 1024 + de];
    g_kv[i] = s;
}

// ---------------- out = kv^T·q / clip(normalizer); overwrites q region in place ----------------
__global__ void __launch_bounds__(256) attnout_kernel() {
    int nblk = blockIdx.x;              // 0..255, 128 columns each
    int bh = blockIdx.y;
    int b = bh >> 3, h = bh & 7;

    __shared__ float qs[32][128];
    __shared__ float kvs[32][32];
    __shared__ float ksA[32];

    int t = threadIdx.x;
    float* qbase = g_qkv + ((size_t)b * MQKV + h * HD) * NSP + (size_t)nblk * 128;

    #pragma unroll
    for (int it = 0; it < 4; it++) {
        int f = t + it * 256;
        int dr = f >> 5, dc = (f & 31) << 2;
        *(float4*)&qs[dr][dc] = *(const float4*)(qbase + (size_t)dr * NSP + dc);
    }
    #pragma unroll
    for (int it = 0; it < 4; it++)
        ((float*)kvs)[t + it * 256] = g_kv[bh * 1024 + t + it * 256];
    if (t < 32) ksA[t] = g_ksumA[b * CCH + h * HD + t];
    __syncthreads();

    int n  = t & 127;
    int e0 = (t >> 7) << 4;             // 0 or 16

    float norm = 0.f;
    #pragma unroll
    for (int d = 0; d < 32; d++) norm = fmaf(qs[d][n], ksA[d], norm);
    float rn = 1.0f / fmaxf(norm, 1e-6f);

    float acc[16];
    #pragma unroll
    for (int e = 0; e < 16; e++) acc[e] = 0.f;
    #pragma unroll
    for (int d = 0; d < 32; d++) {
        float qd = qs[d][n];
        #pragma unroll
        for (int e = 0; e < 16; e++)
            acc[e] = fmaf(qd, kvs[d][e0 + e], acc[e]);
    }
    // safe in-place overwrite: full q tile already staged in smem
    #pragma unroll
    for (int e = 0; e < 16; e++)
        qbase[(size_t)(e0 + e) * NSP + n] = acc[e] * rn;
}

// ---------------- final: y = x + GN2(proj) ----------------
__global__ void final_kernel(const float* __restrict__ x,
                             const float* __restrict__ ow, const float* __restrict__ ob,
                             float* __restrict__ out) {
    const int n4 = NSP / 4;
    const int total = BATCH * CCH * n4;
    for (int i = blockIdx.x * blockDim.x + threadIdx.x; i < total; i += gridDim.x * blockDim.x) {
        int row = i / n4;
        int c = row % CCH, b = row / CCH;
        int g = c / CPG;
        float mu = g_mu2[b * GRP + g], r = g_rstd2[b * GRP + g];
        float sc = r * ow[c];
        float sh = ob[c] - mu * sc;
        float4 xv = ((const float4*)x)[i];
        float4 pv = ((const float4*)g_proj)[i];
        float4 o;
        o.x = xv.x + fmaf(pv.x, sc, sh);
        o.y = xv.y + fmaf(pv.y, sc, sh);
        o.z = xv.z + fmaf(pv.z, sc, sh);
        o.w = xv.w + fmaf(pv.w, sc, sh);
        ((float4*)out)[i] = o;
    }
}

// ---------------- launch ----------------
extern "C" void kernel_launch(void* const* d_in, const int* in_sizes, int n_in,
                              void* d_out, int out_size) {
    const float* x      = (const float*)d_in[0];
    const float* norm_w = (const float*)d_in[1];
    const float* norm_b = (const float*)d_in[2];
    const float* qkv_w  = (const float*)d_in[3];
    const float* qkv_b  = (const float*)d_in[4];
    const float* out_w  = (const float*)d_in[5];
    const float* out_b  = (const float*)d_in[6];
    const float* onw    = (const float*)d_in[7];
    const float* onb    = (const float*)d_in[8];
    float* out = (float*)d_out;

    gn_stats_kernel<0><<<BATCH * GRP, 256>>>(x);
    prep_kernel<<<2, 256>>>(norm_w, norm_b);
    gemm_kernel<0><<<dim3(NSP / 128, MQKV / 128, BATCH), 256>>>(qkv_w, x, qkv_b);
    krowsum_kernel<<<BATCH * CCH, 256>>>();
    kv_kernel<<<dim3(16, KVSPLIT), 256>>>();
    kvreduce_kernel<<<64, 256>>>();
    attnout_kernel<<<dim3(NSP / 128, 16), 256>>>();
    gemm_kernel<1><<<dim3(NSP / 128, CCH / 128, BATCH), 256>>>(out_w, nullptr, out_b);
    gn_stats_kernel<1><<<BATCH * GRP, 256>>>(x /*unused*/);
    final_kernel<<<4096, 256>>>(x, onw, onb, out);
}

// round 2
// speedup vs baseline: 1.8539x; 1.8539x over previous
#include <cuda_runtime.h>
#include <cuda_bf16.h>
#include <cstdint>

// ---------------- problem constants ----------------
#define BATCH 2
#define CCH   256          // channels C
#define NSP   32768        // N = D*H*W = 32^3
#define NHEAD 8
#define HD    32           // head dim
#define GRP   32           // groupnorm groups
#define CPG   8            // channels per group
#define MQKV  768          // 3*C
#define EPS   1e-5f
#define KVSPLIT 64

// ---------------- static scratch ----------------
__device__ float g_qkv[(size_t)BATCH * MQKV * NSP];   // 192 MB: q|k|v, q overwritten by attn-out
__device__ float g_proj[(size_t)BATCH * CCH * NSP];   // 64 MB
__device__ float g_mu1[BATCH * GRP];
__device__ float g_rstd1[BATCH * GRP];
__device__ float g_mu2[BATCH * GRP];
__device__ float g_rstd2[BATCH * GRP];
__device__ float g_scale1[BATCH * CCH];
__device__ float g_shift1[BATCH * CCH];
__device__ float g_invs[BATCH * CCH];
__device__ float g_ksumA[BATCH * CCH];
__device__ float g_kvpart[(size_t)KVSPLIT * 16 * 1024];
__device__ float g_kv[BATCH * NHEAD * HD * HD];

// ---------------- helpers ----------------
__device__ __forceinline__ float warp_sum(float v) {
    #pragma unroll
    for (int o = 16; o; o >>= 1) v += __shfl_xor_sync(0xffffffffu, v, o);
    return v;
}

__device__ __forceinline__ float to_tf32(float x) {
    uint32_t u;
    asm("cvt.rna.tf32.f32 %0, %1;" : "=r"(u) : "f"(x));
    return __uint_as_float(u);
}

__device__ __forceinline__ void mma_tf32(
    float& c0, float& c1, float& c2, float& c3,
    float a0, float a1, float a2, float a3,
    float b0, float b1)
{
    asm volatile(
        "mma.sync.aligned.m16n8k8.row.col.f32.tf32.tf32.f32 "
        "{%0,%1,%2,%3}, {%4,%5,%6,%7}, {%8,%9}, {%0,%1,%2,%3};"
        : "+f"(c0), "+f"(c1), "+f"(c2), "+f"(c3)
        : "r"(__float_as_uint(a0)), "r"(__float_as_uint(a1)),
          "r"(__float_as_uint(a2)), "r"(__float_as_uint(a3)),
          "r"(__float_as_uint(b0)), "r"(__float_as_uint(b1)));
}

// ---------------- group-norm stats ----------------
template<int STAGE>
__global__ void gn_stats_kernel(const float* __restrict__ xsrc) {
    const float* src = (STAGE == 0) ? xsrc : g_proj;
    int grp = blockIdx.x;
    const float4* base = (const float4*)(src + (size_t)grp * CPG * NSP);
    const int M4 = CPG * NSP / 4;
    float s = 0.f, s2 = 0.f;
    for (int i = threadIdx.x; i < M4; i += 256) {
        float4 v = base[i];
        s  += (v.x + v.y) + (v.z + v.w);
        s2 += v.x * v.x + v.y * v.y + v.z * v.z + v.w * v.w;
    }
    __shared__ float sh[8], sh2[8];
    s = warp_sum(s); s2 = warp_sum(s2);
    int w = threadIdx.x >> 5, l = threadIdx.x & 31;
    if (l == 0) { sh[w] = s; sh2[w] = s2; }
    __syncthreads();
    if (w == 0) {
        s  = (l < 8) ? sh[l]  : 0.f;
        s2 = (l < 8) ? sh2[l] : 0.f;
        s = warp_sum(s); s2 = warp_sum(s2);
        if (l == 0) {
            const float inv = 1.0f / (float)(CPG * NSP);
            float mu  = s * inv;
            float var = s2 * inv - mu * mu;
            float rs  = rsqrtf(var + EPS);
            if (STAGE == 0) { g_mu1[grp] = mu; g_rstd1[grp] = rs; }
            else            { g_mu2[grp] = mu; g_rstd2[grp] = rs; }
        }
    }
}

__global__ void prep_kernel(const float* __restrict__ nw, const float* __restrict__ nb) {
    int i = blockIdx.x * 256 + threadIdx.x;
    if (i < BATCH * CCH) {
        int b = i / CCH, c = i % CCH;
        float mu = g_mu1[b * GRP + c / CPG];
        float r  = g_rstd1[b * GRP + c / CPG];
        float sc = r * nw[c];
        g_scale1[i] = sc;
        g_shift1[i] = nb[c] - mu * sc;
    }
}

// ---------------- TF32 tensor-core GEMM: C[M,NSP] = A[M,256] @ B[256,NSP] + bias ----
// MODE 0: B = groupnorm(x) on the fly, C = g_qkv, elu+1 on rows < 512 (q,k)
// MODE 1: B = g_qkv q-region (attn result), C = g_proj
// Block 128x128x(K=256), 256 threads = 8 warps, warp tile 32x64, mma m16n8k8.
#define LDA 36    // As [m][k]  stride (32 + 4)  -> frag LDS conflict-free
#define LDB 136   // Bs [k][n]  stride (128 + 8) -> frag LDS conflict-free

template<int MODE>
__global__ void __launch_bounds__(256) mma_gemm_kernel(
    const float* __restrict__ A, const float* __restrict__ Bsrc,
    const float* __restrict__ bias)
{
    __shared__ float As[128 * LDA];
    __shared__ float Bs[32 * LDB];

    const int bz = blockIdx.z;
    const int mt = blockIdx.y;
    const int nt = blockIdx.x;
    const int t  = threadIdx.x;
    const int warp = t >> 5, lane = t & 31;
    const int wm = warp >> 1;        // 0..3  -> m offset wm*32
    const int wn = warp & 1;         // 0..1  -> n offset wn*64
    const int g  = lane >> 2;        // 0..7
    const int c  = lane & 3;         // 0..3

    const float* Ab = A + (size_t)mt * 128 * CCH;
    const float* Bb;
    float* Cd;
    if (MODE == 0) {
        Bb = Bsrc + (size_t)bz * CCH * NSP + (size_t)nt * 128;
        Cd = g_qkv + ((size_t)bz * MQKV + (size_t)mt * 128) * NSP + (size_t)nt * 128;
    } else {
        Bb = g_qkv + (size_t)bz * MQKV * NSP + (size_t)nt * 128;
        Cd = g_proj + ((size_t)bz * CCH + (size_t)mt * 128) * NSP + (size_t)nt * 128;
    }

    // per-thread load indices (same every tile)
    const int ar  = t >> 1;                 // A row handled, 2 float4 per row? no:
    // A: 128 rows x 8 float4 (32 k) = 1024 float4, 4 per thread
    // f = t + i*256 : ar = f>>3, ak4 = f&7
    // B: 32 rows x 32 float4 (128 n) = 1024 float4, 4 per thread
    // f = t + i*256 : bk = f>>5, bn4 = f&31
    (void)ar;

    float acc[2][8][4];
    #pragma unroll
    for (int i = 0; i < 2; i++)
        #pragma unroll
        for (int j = 0; j < 8; j++)
            #pragma unroll
            for (int q = 0; q < 4; q++) acc[i][j][q] = 0.f;

    float4 pa[4], pb[4];
    float psc[4], psh[4];

    // prefetch tile 0
    #pragma unroll
    for (int i = 0; i < 4; i++) {
        int f = t + i * 256;
        pa[i] = *(const float4*)(Ab + (size_t)(f >> 3) * CCH + ((f & 7) << 2));
        int bk = f >> 5, bn4 = f & 31;
        pb[i] = *(const float4*)(Bb + (size_t)bk * NSP + (bn4 << 2));
        if (MODE == 0) {
            psc[i] = g_scale1[bz * CCH + bk];
            psh[i] = g_shift1[bz * CCH + bk];
        }
    }

    // smem frag base offsets
    const int a_base = (wm * 32 + g) * LDA + c;          // + i2*16*LDA, +8*LDA, +4
    const int b_base = c * LDB + wn * 64 + g;            // + kb*LDB, + j2*8, +4*LDB

    for (int kt = 0; kt < 8; kt++) {
        // store prefetched tile to smem (cvt to tf32; GN affine for MODE 0)
        #pragma unroll
        for (int i = 0; i < 4; i++) {
            int f = t + i * 256;
            float4 a4 = pa[i];
            float4 as = make_float4(to_tf32(a4.x), to_tf32(a4.y), to_tf32(a4.z), to_tf32(a4.w));
            *(float4*)&As[(f >> 3) * LDA + ((f & 7) << 2)] = as;

            float4 b4 = pb[i];
            if (MODE == 0) {
                float sc = psc[i], sh = psh[i];
                b4.x = fmaf(b4.x, sc, sh); b4.y = fmaf(b4.y, sc, sh);
                b4.z = fmaf(b4.z, sc, sh); b4.w = fmaf(b4.w, sc, sh);
            }
            float4 bs = make_float4(to_tf32(b4.x), to_tf32(b4.y), to_tf32(b4.z), to_tf32(b4.w));
            *(float4*)&Bs[(f >> 5) * LDB + ((f & 31) << 2)] = bs;
        }
        __syncthreads();

        // prefetch next tile (overlaps with mma below)
        if (kt < 7) {
            int k0 = (kt + 1) * 32;
            #pragma unroll
            for (int i = 0; i < 4; i++) {
                int f = t + i * 256;
                pa[i] = *(const float4*)(Ab + (size_t)(f >> 3) * CCH + k0 + ((f & 7) << 2));
                int bk = f >> 5, bn4 = f & 31;
                pb[i] = *(const float4*)(Bb + (size_t)(k0 + bk) * NSP + (bn4 << 2));
                if (MODE == 0) {
                    psc[i] = g_scale1[bz * CCH + k0 + bk];
                    psh[i] = g_shift1[bz * CCH + k0 + bk];
                }
            }
        }

        // compute: 4 k-steps of 8
        #pragma unroll
        for (int ks = 0; ks < 4; ks++) {
            const int kb = ks * 8;
            float af[2][4];
            #pragma unroll
            for (int i2 = 0; i2 < 2; i2++) {
                const float* ap = &As[a_base + i2 * 16 * LDA + kb];
                af[i2][0] = ap[0];
                af[i2][1] = ap[8 * LDA];
                af[i2][2] = ap[4];
                af[i2][3] = ap[8 * LDA + 4];
            }
            #pragma unroll
            for (int j2 = 0; j2 < 8; j2++) {
                const float* bp = &Bs[b_base + kb * LDB + j2 * 8];
                float b0 = bp[0];
                float b1 = bp[4 * LDB];
                #pragma unroll
                for (int i2 = 0; i2 < 2; i2++)
                    mma_tf32(acc[i2][j2][0], acc[i2][j2][1], acc[i2][j2][2], acc[i2][j2][3],
                             af[i2][0], af[i2][1], af[i2][2], af[i2][3], b0, b1);
            }
        }
        __syncthreads();
    }

    // epilogue: bias (+ elu for MODE 0 rows < 512)
    #pragma unroll
    for (int i2 = 0; i2 < 2; i2++) {
        int lr0 = wm * 32 + i2 * 16 + g;       // local row of c0,c1
        int o0  = mt * 128 + lr0;
        int o1  = o0 + 8;
        float bi0 = bias[o0], bi1 = bias[o1];
        #pragma unroll
        for (int j2 = 0; j2 < 8; j2++) {
            int lc = wn * 64 + j2 * 8 + 2 * c;
            float v0 = acc[i2][j2][0] + bi0;
            float v1 = acc[i2][j2][1] + bi0;
            float v2 = acc[i2][j2][2] + bi1;
            float v3 = acc[i2][j2][3] + bi1;
            if (MODE == 0 && o0 < 512) {
                v0 = (v0 > 0.f) ? (v0 + 1.f) : __expf(v0);
                v1 = (v1 > 0.f) ? (v1 + 1.f) : __expf(v1);
            }
            if (MODE == 0 && o1 < 512) {
                v2 = (v2 > 0.f) ? (v2 + 1.f) : __expf(v2);
                v3 = (v3 > 0.f) ? (v3 + 1.f) : __expf(v3);
            }
            *(float2*)(Cd + (size_t)lr0 * NSP + lc)       = make_float2(v0, v1);
            *(float2*)(Cd + (size_t)(lr0 + 8) * NSP + lc) = make_float2(v2, v3);
        }
    }
}

// ---------------- k row-sums ----------------
__global__ void krowsum_kernel() {
    int row = blockIdx.x;
    int b = row >> 8, r = row & 255;
    const float4* base = (const float4*)(g_qkv + ((size_t)b * MQKV + 256 + r) * NSP);
    float s = 0.f;
    for (int i = threadIdx.x; i < NSP / 4; i += 256) {
        float4 v = base[i];
        s += (v.x + v.y) + (v.z + v.w);
    }
    __shared__ float sh[8];
    s = warp_sum(s);
    int w = threadIdx.x >> 5, l = threadIdx.x & 31;
    if (l == 0) sh[w] = s;
    __syncthreads();
    if (w == 0) {
        s = (l < 8) ? sh[l] : 0.f;
        s = warp_sum(s);
        if (l == 0) {
            float cs = fmaxf(s, 1e-6f);
            g_invs[row]  = 1.0f / cs;
            g_ksumA[row] = s / cs;
        }
    }
}

// ---------------- kv = (k/clip)·v^T, split-K partials ----------------
__global__ void __launch_bounds__(256) kv_kernel() {
    int bh = blockIdx.x;
    int split = blockIdx.y;
    int b = bh >> 3, h = bh & 7;

    __shared__ float ks[32][129];
    __shared__ float vs[32][129];

    const float* kbase = g_qkv + ((size_t)b * MQKV + 256 + h * HD) * NSP + (size_t)split * 512;
    const float* vbase = g_qkv + ((size_t)b * MQKV + 512 + h * HD) * NSP + (size_t)split * 512;

    int t = threadIdx.x;
    int d0 = (t >> 4) << 1;
    int e0 = (t & 15) << 1;

    float a00 = 0.f, a01 = 0.f, a10 = 0.f, a11 = 0.f;

    for (int ch = 0; ch < 4; ch++) {
        __syncthreads();
        #pragma unroll
        for (int it = 0; it < 4; it++) {
            int f = t + it * 256;
            int dr = f >> 5, dc = (f & 31) << 2;
            float4 kk = *(const float4*)(kbase + (size_t)dr * NSP + ch * 128 + dc);
            ks[dr][dc + 0] = kk.x; ks[dr][dc + 1] = kk.y;
            ks[dr][dc + 2] = kk.z; ks[dr][dc + 3] = kk.w;
            float4 vv = *(const float4*)(vbase + (size_t)dr * NSP + ch * 128 + dc);
            vs[dr][dc + 0] = vv.x; vs[dr][dc + 1] = vv.y;
            vs[dr][dc + 2] = vv.z; vs[dr][dc + 3] = vv.w;
        }
        __syncthreads();
        #pragma unroll 4
        for (int n = 0; n < 128; n++) {
            float k0v = ks[d0][n],     k1v = ks[d0 + 1][n];
            float v0v = vs[e0][n],     v1v = vs[e0 + 1][n];
            a00 = fmaf(k0v, v0v, a00); a01 = fmaf(k0v, v1v, a01);
            a10 = fmaf(k1v, v0v, a10); a11 = fmaf(k1v, v1v, a11);
        }
    }

    float i0 = g_invs[b * CCH + h * HD + d0];
    float i1 = g_invs[b * CCH + h * HD + d0 + 1];
    float* dst = g_kvpart + ((size_t)split * 16 + bh) * 1024;
    dst[(d0    ) * 32 + e0    ] = a00 * i0;
    dst[(d0    ) * 32 + e0 + 1] = a01 * i0;
    dst[(d0 + 1) * 32 + e0    ] = a10 * i1;
    dst[(d0 + 1) * 32 + e0 + 1] = a11 * i1;
}

__global__ void kvreduce_kernel() {
    int i = blockIdx.x * 256 + threadIdx.x;
    if (i >= 16 * 1024) return;
    int bh = i >> 10, de = i & 1023;
    float s = 0.f;
    #pragma unroll 8
    for (int sp = 0; sp < KVSPLIT; sp++)
        s += g_kvpart[((size_t)sp * 16 + bh) * 1024 + de];
    g_kv[i] = s;
}

// ---------------- out = kv^T·q / clip(normalizer); overwrites q in place ----------
__global__ void __launch_bounds__(256) attnout_kernel() {
    int nblk = blockIdx.x;
    int bh = blockIdx.y;
    int b = bh >> 3, h = bh & 7;

    __shared__ float qs[32][128];
    __shared__ float kvs[32][32];
    __shared__ float ksA[32];

    int t = threadIdx.x;
    float* qbase = g_qkv + ((size_t)b * MQKV + h * HD) * NSP + (size_t)nblk * 128;

    #pragma unroll
    for (int it = 0; it < 4; it++) {
        int f = t + it * 256;
        int dr = f >> 5, dc = (f & 31) << 2;
        *(float4*)&qs[dr][dc] = *(const float4*)(qbase + (size_t)dr * NSP + dc);
    }
    #pragma unroll
    for (int it = 0; it < 4; it++)
        ((float*)kvs)[t + it * 256] = g_kv[bh * 1024 + t + it * 256];
    if (t < 32) ksA[t] = g_ksumA[b * CCH + h * HD + t];
    __syncthreads();

    int n  = t & 127;
    int e0 = (t >> 7) << 4;

    float norm = 0.f;
    #pragma unroll
    for (int d = 0; d < 32; d++) norm = fmaf(qs[d][n], ksA[d], norm);
    float rn = 1.0f / fmaxf(norm, 1e-6f);

    float acc[16];
    #pragma unroll
    for (int e = 0; e < 16; e++) acc[e] = 0.f;
    #pragma unroll
    for (int d = 0; d < 32; d++) {
        float qd = qs[d][n];
        #pragma unroll
        for (int e = 0; e < 16; e++)
            acc[e] = fmaf(qd, kvs[d][e0 + e], acc[e]);
    }
    #pragma unroll
    for (int e = 0; e < 16; e++)
        qbase[(size_t)(e0 + e) * NSP + n] = acc[e] * rn;
}

// ---------------- final: y = x + GN2(proj) ----------------
__global__ void final_kernel(const float* __restrict__ x,
                             const float* __restrict__ ow, const float* __restrict__ ob,
                             float* __restrict__ out) {
    const int n4 = NSP / 4;
    const int total = BATCH * CCH * n4;
    for (int i = blockIdx.x * blockDim.x + threadIdx.x; i < total; i += gridDim.x * blockDim.x) {
        int row = i / n4;
        int c = row % CCH, b = row / CCH;
        int g = c / CPG;
        float mu = g_mu2[b * GRP + g], r = g_rstd2[b * GRP + g];
        float sc = r * ow[c];
        float sh = ob[c] - mu * sc;
        float4 xv = ((const float4*)x)[i];
        float4 pv = ((const float4*)g_proj)[i];
        float4 o;
        o.x = xv.x + fmaf(pv.x, sc, sh);
        o.y = xv.y + fmaf(pv.y, sc, sh);
        o.z = xv.z + fmaf(pv.z, sc, sh);
        o.w = xv.w + fmaf(pv.w, sc, sh);
        ((float4*)out)[i] = o;
    }
}

// ---------------- launch ----------------
extern "C" void kernel_launch(void* const* d_in, const int* in_sizes, int n_in,
                              void* d_out, int out_size) {
    const float* x      = (const float*)d_in[0];
    const float* norm_w = (const float*)d_in[1];
    const float* norm_b = (const float*)d_in[2];
    const float* qkv_w  = (const float*)d_in[3];
    const float* qkv_b  = (const float*)d_in[4];
    const float* out_w  = (const float*)d_in[5];
    const float* out_b  = (const float*)d_in[6];
    const float* onw    = (const float*)d_in[7];
    const float* onb    = (const float*)d_in[8];
    float* out = (float*)d_out;

    gn_stats_kernel<0><<<BATCH * GRP, 256>>>(x);
    prep_kernel<<<2, 256>>>(norm_w, norm_b);
    mma_gemm_kernel<0><<<dim3(NSP / 128, MQKV / 128, BATCH), 256>>>(qkv_w, x, qkv_b);
    krowsum_kernel<<<BATCH * CCH, 256>>>();
    kv_kernel<<<dim3(16, KVSPLIT), 256>>>();
    kvreduce_kernel<<<64, 256>>>();
    attnout_kernel<<<dim3(NSP / 128, 16), 256>>>();
    mma_gemm_kernel<1><<<dim3(NSP / 128, CCH / 128, BATCH), 256>>>(out_w, nullptr, out_b);
    gn_stats_kernel<1><<<BATCH * GRP, 256>>>(x /*unused*/);
    final_kernel<<<4096, 256>>>(x, onw, onb, out);
}

// round 4
// speedup vs baseline: 1.9469x; 1.0502x over previous
#include <cuda_runtime.h>
#include <cuda_bf16.h>
#include <cstdint>

// ---------------- problem constants ----------------
#define BATCH 2
#define CCH   256
#define NSP   32768
#define NHEAD 8
#define HD    32
#define GRP   32
#define CPG   8
#define MQKV  768
#define EPS   1e-5f
#define KVSPLIT 64

// ---------------- static scratch ----------------
__device__ float g_qkv[(size_t)BATCH * MQKV * NSP];   // q|k|v ; q overwritten by attn-out
__device__ float g_proj[(size_t)BATCH * CCH * NSP];
__device__ float g_mu1[BATCH * GRP];
__device__ float g_rstd1[BATCH * GRP];
__device__ float g_mu2[BATCH * GRP];
__device__ float g_rstd2[BATCH * GRP];
__device__ float g_scale1[BATCH * CCH];
__device__ float g_shift1[BATCH * CCH];
__device__ float g_a2[(size_t)BATCH * MQKV * CCH];    // folded A' = W * sc   (per batch)
__device__ float g_bias2[BATCH * MQKV];               // folded bias' = W@sh + qkv_b
__device__ float g_ksumA[BATCH * CCH];
__device__ float g_kvpart[(size_t)KVSPLIT * 16 * 1024];
__device__ float g_ksump[KVSPLIT * 16 * 32];
__device__ float g_kv[BATCH * NHEAD * HD * HD];

// ---------------- helpers ----------------
__device__ __forceinline__ float warp_sum(float v) {
    #pragma unroll
    for (int o = 16; o; o >>= 1) v += __shfl_xor_sync(0xffffffffu, v, o);
    return v;
}
__device__ __forceinline__ float to_tf32(float x) {
    uint32_t u;
    asm("cvt.rna.tf32.f32 %0, %1;" : "=r"(u) : "f"(x));
    return __uint_as_float(u);
}
__device__ __forceinline__ uint32_t smem_u32(const void* p) {
    uint32_t a;
    asm("{ .reg .u64 t; cvta.to.shared.u64 t, %1; cvt.u32.u64 %0, t; }" : "=r"(a) : "l"(p));
    return a;
}
__device__ __forceinline__ void cp16(uint32_t saddr, const void* g) {
    asm volatile("cp.async.ca.shared.global [%0], [%1], 16;" :: "r"(saddr), "l"(g) : "memory");
}
__device__ __forceinline__ void cp_commit() {
    asm volatile("cp.async.commit_group;" ::: "memory");
}
__device__ __forceinline__ void cp_wait0() {
    asm volatile("cp.async.wait_group 0;" ::: "memory");
}

__device__ __forceinline__ void mma_tf32(
    float& c0, float& c1, float& c2, float& c3,
    float a0, float a1, float a2, float a3,
    float b0, float b1)
{
    asm volatile(
        "mma.sync.aligned.m16n8k8.row.col.f32.tf32.tf32.f32 "
        "{%0,%1,%2,%3}, {%4,%5,%6,%7}, {%8,%9}, {%0,%1,%2,%3};"
        : "+f"(c0), "+f"(c1), "+f"(c2), "+f"(c3)
        : "r"(__float_as_uint(a0)), "r"(__float_as_uint(a1)),
          "r"(__float_as_uint(a2)), "r"(__float_as_uint(a3)),
          "r"(__float_as_uint(b0)), "r"(__float_as_uint(b1)));
}

// ---------------- group-norm stats ----------------
template<int STAGE>
__global__ void gn_stats_kernel(const float* __restrict__ xsrc) {
    const float* src = (STAGE == 0) ? xsrc : g_proj;
    int grp = blockIdx.x;
    const float4* base = (const float4*)(src + (size_t)grp * CPG * NSP);
    const int M4 = CPG * NSP / 4;
    float s = 0.f, s2 = 0.f;
    for (int i = threadIdx.x; i < M4; i += 256) {
        float4 v = base[i];
        s  += (v.x + v.y) + (v.z + v.w);
        s2 += v.x * v.x + v.y * v.y + v.z * v.z + v.w * v.w;
    }
    __shared__ float sh[8], sh2[8];
    s = warp_sum(s); s2 = warp_sum(s2);
    int w = threadIdx.x >> 5, l = threadIdx.x & 31;
    if (l == 0) { sh[w] = s; sh2[w] = s2; }
    __syncthreads();
    if (w == 0) {
        s  = (l < 8) ? sh[l]  : 0.f;
        s2 = (l < 8) ? sh2[l] : 0.f;
        s = warp_sum(s); s2 = warp_sum(s2);
        if (l == 0) {
            const float inv = 1.0f / (float)(CPG * NSP);
            float mu  = s * inv;
            float var = s2 * inv - mu * mu;
            float rs  = rsqrtf(var + EPS);
            if (STAGE == 0) { g_mu1[grp] = mu; g_rstd1[grp] = rs; }
            else            { g_mu2[grp] = mu; g_rstd2[grp] = rs; }
        }
    }
}

__global__ void prep_kernel(const float* __restrict__ nw, const float* __restrict__ nb) {
    int i = blockIdx.x * 256 + threadIdx.x;
    if (i < BATCH * CCH) {
        int b = i / CCH, c = i % CCH;
        float mu = g_mu1[b * GRP + c / CPG];
        float r  = g_rstd1[b * GRP + c / CPG];
        float sc = r * nw[c];
        g_scale1[i] = sc;
        g_shift1[i] = nb[c] - mu * sc;
    }
}

// fold GN1 affine into weights: A' = W*sc, bias' = W@sh + qkv_b (per batch)
__global__ void prep2_kernel(const float* __restrict__ qkv_w, const float* __restrict__ qkv_b) {
    int o = blockIdx.x, b = blockIdx.y;
    int c = threadIdx.x;
    float w  = qkv_w[o * CCH + c];
    float sc = g_scale1[b * CCH + c];
    float sh = g_shift1[b * CCH + c];
    g_a2[((size_t)b * MQKV + o) * CCH + c] = w * sc;
    float v = w * sh;
    __shared__ float red[8];
    v = warp_sum(v);
    int wp = c >> 5, l = c & 31;
    if (l == 0) red[wp] = v;
    __syncthreads();
    if (c == 0) {
        float s = 0.f;
        #pragma unroll
        for (int i = 0; i < 8; i++) s += red[i];
        g_bias2[b * MQKV + o] = s + qkv_b[o];
    }
}

// ======== tf32 mma.sync GEMM, cp.async double-buffered ========
// C[M,NSP] = A[M,256] @ B[256,NSP] + bias
// MODE 0: A=g_a2[bz], B=x[bz], C=g_qkv[bz], elu+1 on rows<512
// MODE 1: A=out_w,    B=q region,  C=g_proj[bz]
#define LDA 36
#define LDB 136
#define ACHUNK (128 * LDA)          // floats
#define BCHUNK (32 * LDB)
#define SMEM_BYTES ((2 * ACHUNK + 2 * BCHUNK) * 4)   // 71680

template<int MODE>
__global__ void __launch_bounds__(256) mma_gemm_kernel(
    const float* __restrict__ Aarg, const float* __restrict__ Bsrc,
    const float* __restrict__ bias_arg)
{
    extern __shared__ float smf[];
    const uint32_t sbase = smem_u32(smf);
    float* Asm[2] = { smf,              smf + ACHUNK };
    float* Bsm[2] = { smf + 2*ACHUNK,   smf + 2*ACHUNK + BCHUNK };
    const uint32_t aAddr[2] = { sbase,                       sbase + ACHUNK*4 };
    const uint32_t bAddr[2] = { sbase + 2*ACHUNK*4,          sbase + (2*ACHUNK + BCHUNK)*4 };

    const int bz = blockIdx.z;
    const int mt = blockIdx.y;
    const int nt = blockIdx.x;
    const int t  = threadIdx.x;
    const int warp = t >> 5, lane = t & 31;
    const int wm = warp >> 1;
    const int wn = warp & 1;
    const int g  = lane >> 2;
    const int c  = lane & 3;

    const float* Ab;
    const float* Bb;
    const float* bias;
    float* Cd;
    if (MODE == 0) {
        Ab   = g_a2 + (size_t)bz * MQKV * CCH + (size_t)mt * 128 * CCH;
        bias = g_bias2 + bz * MQKV;
        Bb   = Bsrc + (size_t)bz * CCH * NSP + (size_t)nt * 128;
        Cd   = g_qkv + ((size_t)bz * MQKV + (size_t)mt * 128) * NSP + (size_t)nt * 128;
    } else {
        Ab   = Aarg + (size_t)mt * 128 * CCH;
        bias = bias_arg;
        Bb   = g_qkv + (size_t)bz * MQKV * NSP + (size_t)nt * 128;
        Cd   = g_proj + ((size_t)bz * CCH + (size_t)mt * 128) * NSP + (size_t)nt * 128;
    }

    float acc[2][8][4];
    #pragma unroll
    for (int i = 0; i < 2; i++)
        #pragma unroll
        for (int j = 0; j < 8; j++)
            #pragma unroll
            for (int q = 0; q < 4; q++) acc[i][j][q] = 0.f;

    // chunk loader: A 128x32, B 32x128, 4+4 cp.async of 16B per thread
    auto load_chunk = [&](int ch, int buf) {
        #pragma unroll
        for (int i = 0; i < 4; i++) {
            int f = t + i * 256;
            int m = f >> 3, cc = f & 7;
            cp16(aAddr[buf] + (uint32_t)(m * LDA + cc * 4) * 4,
                 Ab + (size_t)m * CCH + ch * 32 + cc * 4);
            int k = f >> 5, n4 = f & 31;
            cp16(bAddr[buf] + (uint32_t)(k * LDB + n4 * 4) * 4,
                 Bb + (size_t)(ch * 32 + k) * NSP + n4 * 4);
        }
        cp_commit();
    };

    load_chunk(0, 0);

    const int a_base = (wm * 32 + g) * LDA + c;
    const int b_base = c * LDB + wn * 64 + g;

    #pragma unroll 1
    for (int kt = 0; kt < 8; kt++) {
        int b = kt & 1;
        cp_wait0();
        __syncthreads();
        if (kt < 7) load_chunk(kt + 1, 1 - b);

        const float* As = Asm[b];
        const float* Bs = Bsm[b];
        #pragma unroll
        for (int ks = 0; ks < 4; ks++) {
            const int kb = ks * 8;
            float af[2][4];
            #pragma unroll
            for (int i2 = 0; i2 < 2; i2++) {
                const float* ap = &As[a_base + i2 * 16 * LDA + kb];
                af[i2][0] = to_tf32(ap[0]);
                af[i2][1] = to_tf32(ap[8 * LDA]);
                af[i2][2] = to_tf32(ap[4]);
                af[i2][3] = to_tf32(ap[8 * LDA + 4]);
            }
            #pragma unroll
            for (int j2 = 0; j2 < 8; j2++) {
                const float* bp = &Bs[b_base + kb * LDB + j2 * 8];
                float b0 = to_tf32(bp[0]);
                float b1 = to_tf32(bp[4 * LDB]);
                #pragma unroll
                for (int i2 = 0; i2 < 2; i2++)
                    mma_tf32(acc[i2][j2][0], acc[i2][j2][1], acc[i2][j2][2], acc[i2][j2][3],
                             af[i2][0], af[i2][1], af[i2][2], af[i2][3], b0, b1);
            }
        }
        __syncthreads();
    }

    // epilogue: bias (+ elu for MODE 0 rows < 512)
    #pragma unroll
    for (int i2 = 0; i2 < 2; i2++) {
        int lr0 = wm * 32 + i2 * 16 + g;
        int o0  = mt * 128 + lr0;
        int o1  = o0 + 8;
        float bi0 = bias[o0], bi1 = bias[o1];
        #pragma unroll
        for (int j2 = 0; j2 < 8; j2++) {
            int lc = wn * 64 + j2 * 8 + 2 * c;
            float v0 = acc[i2][j2][0] + bi0;
            float v1 = acc[i2][j2][1] + bi0;
            float v2 = acc[i2][j2][2] + bi1;
            float v3 = acc[i2][j2][3] + bi1;
            if (MODE == 0 && o0 < 512) {
                v0 = (v0 > 0.f) ? (v0 + 1.f) : __expf(v0);
                v1 = (v1 > 0.f) ? (v1 + 1.f) : __expf(v1);
            }
            if (MODE == 0 && o1 < 512) {
                v2 = (v2 > 0.f) ? (v2 + 1.f) : __expf(v2);
                v3 = (v3 > 0.f) ? (v3 + 1.f) : __expf(v3);
            }
            *(float2*)(Cd + (size_t)lr0 * NSP + lc)       = make_float2(v0, v1);
            *(float2*)(Cd + (size_t)(lr0 + 8) * NSP + lc) = make_float2(v2, v3);
        }
    }
}

// ---------------- kv partials + k rowsum partials (fused) ----------------
__global__ void __launch_bounds__(256) kv_kernel() {
    int bh = blockIdx.x;
    int split = blockIdx.y;
    int b = bh >> 3, h = bh & 7;

    __shared__ float ks[32][129];
    __shared__ float vs[32][129];

    const float* kbase = g_qkv + ((size_t)b * MQKV + 256 + h * HD) * NSP + (size_t)split * 512;
    const float* vbase = g_qkv + ((size_t)b * MQKV + 512 + h * HD) * NSP + (size_t)split * 512;

    int t = threadIdx.x;
    int d0 = (t >> 4) << 1;
    int e0 = (t & 15) << 1;

    float a00 = 0.f, a01 = 0.f, a10 = 0.f, a11 = 0.f;
    float s0 = 0.f, s1 = 0.f;

    for (int ch = 0; ch < 4; ch++) {
        __syncthreads();
        #pragma unroll
        for (int it = 0; it < 4; it++) {
            int f = t + it * 256;
            int dr = f >> 5, dc = (f & 31) << 2;
            float4 kk = *(const float4*)(kbase + (size_t)dr * NSP + ch * 128 + dc);
            ks[dr][dc + 0] = kk.x; ks[dr][dc + 1] = kk.y;
            ks[dr][dc + 2] = kk.z; ks[dr][dc + 3] = kk.w;
            float4 vv = *(const float4*)(vbase + (size_t)dr * NSP + ch * 128 + dc);
            vs[dr][dc + 0] = vv.x; vs[dr][dc + 1] = vv.y;
            vs[dr][dc + 2] = vv.z; vs[dr][dc + 3] = vv.w;
        }
        __syncthreads();
        #pragma unroll 4
        for (int n = 0; n < 128; n++) {
            float k0v = ks[d0][n],     k1v = ks[d0 + 1][n];
            float v0v = vs[e0][n],     v1v = vs[e0 + 1][n];
            a00 = fmaf(k0v, v0v, a00); a01 = fmaf(k0v, v1v, a01);
            a10 = fmaf(k1v, v0v, a10); a11 = fmaf(k1v, v1v, a11);
            s0 += k0v; s1 += k1v;
        }
    }

    float* dst = g_kvpart + ((size_t)split * 16 + bh) * 1024;
    dst[(d0    ) * 32 + e0    ] = a00;
    dst[(d0    ) * 32 + e0 + 1] = a01;
    dst[(d0 + 1) * 32 + e0    ] = a10;
    dst[(d0 + 1) * 32 + e0 + 1] = a11;
    if (e0 == 0) {
        g_ksump[(split * 16 + bh) * 32 + d0]     = s0;
        g_ksump[(split * 16 + bh) * 32 + d0 + 1] = s1;
    }
}

// reduce kv partials + rowsums; apply 1/clip scaling; emit ksumA
__global__ void kvreduce_kernel() {
    int i = blockIdx.x * 256 + threadIdx.x;
    if (i >= 16 * 1024) return;
    int bh = i >> 10, de = i & 1023;
    int d = de >> 5, e = de & 31;
    float rs = 0.f;
    #pragma unroll 8
    for (int sp = 0; sp < KVSPLIT; sp++)
        rs += g_ksump[(sp * 16 + bh) * 32 + d];
    float cs = fmaxf(rs, 1e-6f);
    float inv = 1.0f / cs;
    float s = 0.f;
    #pragma unroll 8
    for (int sp = 0; sp < KVSPLIT; sp++)
        s += g_kvpart[((size_t)sp * 16 + bh) * 1024 + de];
    g_kv[i] = s * inv;
    if (e == 0) {
        int b = bh >> 3, h = bh & 7;
        g_ksumA[b * CCH + h * HD + d] = rs * inv;
    }
}

// ---------------- out = kv^T·q / clip(normalizer); overwrites q in place ----------
__global__ void __launch_bounds__(256) attnout_kernel() {
    int nblk = blockIdx.x;
    int bh = blockIdx.y;
    int b = bh >> 3, h = bh & 7;

    __shared__ float qs[32][128];
    __shared__ float kvs[32][32];
    __shared__ float ksA[32];

    int t = threadIdx.x;
    float* qbase = g_qkv + ((size_t)b * MQKV + h * HD) * NSP + (size_t)nblk * 128;

    #pragma unroll
    for (int it = 0; it < 4; it++) {
        int f = t + it * 256;
        int dr = f >> 5, dc = (f & 31) << 2;
        *(float4*)&qs[dr][dc] = *(const float4*)(qbase + (size_t)dr * NSP + dc);
    }
    #pragma unroll
    for (int it = 0; it < 4; it++)
        ((float*)kvs)[t + it * 256] = g_kv[bh * 1024 + t + it * 256];
    if (t < 32) ksA[t] = g_ksumA[b * CCH + h * HD + t];
    __syncthreads();

    int n  = t & 127;
    int e0 = (t >> 7) << 4;

    float norm = 0.f;
    #pragma unroll
    for (int d = 0; d < 32; d++) norm = fmaf(qs[d][n], ksA[d], norm);
    float rn = 1.0f / fmaxf(norm, 1e-6f);

    float acc[16];
    #pragma unroll
    for (int e = 0; e < 16; e++) acc[e] = 0.f;
    #pragma unroll
    for (int d = 0; d < 32; d++) {
        float qd = qs[d][n];
        #pragma unroll
        for (int e = 0; e < 16; e++)
            acc[e] = fmaf(qd, kvs[d][e0 + e], acc[e]);
    }
    #pragma unroll
    for (int e = 0; e < 16; e++)
        qbase[(size_t)(e0 + e) * NSP + n] = acc[e] * rn;
}

// ---------------- final: y = x + GN2(proj) ----------------
__global__ void final_kernel(const float* __restrict__ x,
                             const float* __restrict__ ow, const float* __restrict__ ob,
                             float* __restrict__ out) {
    const int n4 = NSP / 4;
    const int total = BATCH * CCH * n4;
    for (int i = blockIdx.x * blockDim.x + threadIdx.x; i < total; i += gridDim.x * blockDim.x) {
        int row = i / n4;
        int c = row % CCH, b = row / CCH;
        int g = c / CPG;
        float mu = g_mu2[b * GRP + g], r = g_rstd2[b * GRP + g];
        float sc = r * ow[c];
        float sh = ob[c] - mu * sc;
        float4 xv = ((const float4*)x)[i];
        float4 pv = ((const float4*)g_proj)[i];
        float4 o;
        o.x = xv.x + fmaf(pv.x, sc, sh);
        o.y = xv.y + fmaf(pv.y, sc, sh);
        o.z = xv.z + fmaf(pv.z, sc, sh);
        o.w = xv.w + fmaf(pv.w, sc, sh);
        ((float4*)out)[i] = o;
    }
}

// ---------------- launch ----------------
extern "C" void kernel_launch(void* const* d_in, const int* in_sizes, int n_in,
                              void* d_out, int out_size) {
    const float* x      = (const float*)d_in[0];
    const float* norm_w = (const float*)d_in[1];
    const float* norm_b = (const float*)d_in[2];
    const float* qkv_w  = (const float*)d_in[3];
    const float* qkv_b  = (const float*)d_in[4];
    const float* out_w  = (const float*)d_in[5];
    const float* out_b  = (const float*)d_in[6];
    const float* onw    = (const float*)d_in[7];
    const float* onb    = (const float*)d_in[8];
    float* out = (float*)d_out;

    cudaFuncSetAttribute(mma_gemm_kernel<0>, cudaFuncAttributeMaxDynamicSharedMemorySize, SMEM_BYTES);
    cudaFuncSetAttribute(mma_gemm_kernel<1>, cudaFuncAttributeMaxDynamicSharedMemorySize, SMEM_BYTES);

    gn_stats_kernel<0><<<BATCH * GRP, 256>>>(x);
    prep_kernel<<<2, 256>>>(norm_w, norm_b);
    prep2_kernel<<<dim3(MQKV, BATCH), 256>>>(qkv_w, qkv_b);
    mma_gemm_kernel<0><<<dim3(NSP / 128, MQKV / 128, BATCH), 256, SMEM_BYTES>>>(nullptr, x, nullptr);
    kv_kernel<<<dim3(16, KVSPLIT), 256>>>();
    kvreduce_kernel<<<64, 256>>>();
    attnout_kernel<<<dim3(NSP / 128, 16), 256>>>();
    mma_gemm_kernel<1><<<dim3(NSP / 128, CCH / 128, BATCH), 256, SMEM_BYTES>>>(out_w, nullptr, out_b);
    gn_stats_kernel<1><<<BATCH * GRP, 256>>>(x /*unused*/);
    final_kernel<<<4096, 256>>>(x, onw, onb, out);
}